// round 12
// baseline (speedup 1.0000x reference)
#include <cuda_runtime.h>
#include <cuda_bf16.h>
#include <cuda_fp16.h>
#include <math.h>

#define B_   16
#define C_   128
#define N_   1024
#define H_   4
#define D_   32
#define CN   (C_*N_)
#define LOG2E 1.4426950408889634f

typedef unsigned short ushort_t;

// ---------------- scratch (device globals; no allocations) ----------------
__device__ float g_conv[3][B_*CN];        // conv outputs, [p][b][c][n]
__device__ float g_part2[384][2];         // conv-block partial sums
__device__ ushort_t g_bias4[H_*N_*N_];    // [h][n][m]  (bf16 bits, pre-scaled by log2e)

// padded input, transposed: [b][sp_pad(34*40)][ci(128)], hi/lo bf16 bits
__device__ __align__(16) ushort_t g_xpad_hi[B_*34*40*C_];
__device__ __align__(16) ushort_t g_xpad_lo[B_*34*40*C_];
// weights: [p][((ky*3+kx)*128+co)*128+ci]
__device__ __align__(16) __nv_bfloat16 g_w_hi[3][9*128*128];
__device__ __align__(16) __nv_bfloat16 g_w_lo[3][9*128*128];
// out_w split: [co][ci]
__device__ __align__(16) ushort_t g_w2_hi[128*128];
__device__ __align__(16) ushort_t g_w2_lo[128*128];

// attention operands.  Q pre-scaled by log2e (bf16 hi/lo); V single fp16.
__device__ __align__(16) ushort_t g_q_hi[64*N_*D_];   // [bh][n][d]
__device__ __align__(16) ushort_t g_q_lo[64*N_*D_];
__device__ __align__(16) ushort_t g_k_hi[64*N_*D_];   // [bh][n][d]
__device__ __align__(16) ushort_t g_k_lo[64*N_*D_];
__device__ __align__(16) ushort_t g_v16[64*D_*N_];    // [bh][d][n]  fp16 bits
// attention output, bf16 hi/lo: [b][n][c]
__device__ __align__(16) ushort_t g_ao_hi[B_*N_*C_];
__device__ __align__(16) ushort_t g_ao_lo[B_*N_*C_];

// =====================================================================
// helpers
// =====================================================================
__device__ __forceinline__ void mma_bf16(float* d, const unsigned* A,
                                         unsigned b0, unsigned b1)
{
    asm volatile(
        "mma.sync.aligned.m16n8k16.row.col.f32.bf16.bf16.f32 "
        "{%0,%1,%2,%3},{%4,%5,%6,%7},{%8,%9},{%0,%1,%2,%3};"
        : "+f"(d[0]), "+f"(d[1]), "+f"(d[2]), "+f"(d[3])
        : "r"(A[0]), "r"(A[1]), "r"(A[2]), "r"(A[3]), "r"(b0), "r"(b1));
}

__device__ __forceinline__ void mma_fp16(float* d, const unsigned* A,
                                         unsigned b0, unsigned b1)
{
    asm volatile(
        "mma.sync.aligned.m16n8k16.row.col.f32.f16.f16.f32 "
        "{%0,%1,%2,%3},{%4,%5,%6,%7},{%8,%9},{%0,%1,%2,%3};"
        : "+f"(d[0]), "+f"(d[1]), "+f"(d[2]), "+f"(d[3])
        : "r"(A[0]), "r"(A[1]), "r"(A[2]), "r"(A[3]), "r"(b0), "r"(b1));
}

__device__ __forceinline__ void ldmatrix_x4(unsigned* r, const ushort_t* p)
{
    unsigned addr = (unsigned)__cvta_generic_to_shared((void*)p);
    asm volatile("ldmatrix.sync.aligned.m8n8.x4.shared.b16 {%0,%1,%2,%3}, [%4];"
        : "=r"(r[0]), "=r"(r[1]), "=r"(r[2]), "=r"(r[3]) : "r"(addr));
}

__device__ __forceinline__ void cp_async16(void* smem, const void* gmem)
{
    unsigned s = (unsigned)__cvta_generic_to_shared(smem);
    asm volatile("cp.async.cg.shared.global [%0], [%1], 16;" :: "r"(s), "l"(gmem));
}
__device__ __forceinline__ void cp_async_commit(){ asm volatile("cp.async.commit_group;"); }
__device__ __forceinline__ void cp_async_wait0(){ asm volatile("cp.async.wait_group 0;" ::: "memory"); }
__device__ __forceinline__ void cp_async_wait1(){ asm volatile("cp.async.wait_group 1;" ::: "memory"); }

__device__ __forceinline__ unsigned packbf(float hi_elem, float lo_elem)
{
    unsigned d;
    asm("cvt.rn.bf16x2.f32 %0, %1, %2;" : "=r"(d) : "f"(hi_elem), "f"(lo_elem));
    return d;
}
__device__ __forceinline__ unsigned packh(float hi_elem, float lo_elem)
{
    unsigned d;
    asm("cvt.rn.f16x2.f32 %0, %1, %2;" : "=r"(d) : "f"(hi_elem), "f"(lo_elem));
    return d;
}
__device__ __forceinline__ float upperf(unsigned u){ return __uint_as_float(u & 0xffff0000u); }
__device__ __forceinline__ float lowerf(unsigned u){ return __uint_as_float(u << 16); }
__device__ __forceinline__ float hhi(unsigned u)
{
    __half2 h = *reinterpret_cast<__half2*>(&u);
    return __half2float(h.y);
}
__device__ __forceinline__ float hlo(unsigned u)
{
    __half2 h = *reinterpret_cast<__half2*>(&u);
    return __half2float(h.x);
}
__device__ __forceinline__ float ex2(float x)
{
    float r;
    asm("ex2.approx.ftz.f32 %0, %1;" : "=f"(r) : "f"(x));
    return r;
}

// =====================================================================
// prep_all
// =====================================================================
__global__ __launch_bounds__(256) void prep_all_kernel(
    const float* __restrict__ x,
    const float* __restrict__ wq, const float* __restrict__ wk,
    const float* __restrict__ wv, const float* __restrict__ w2,
    const float* __restrict__ table, const int* __restrict__ rel_index)
{
    const int blk = blockIdx.x;
    const int tid = threadIdx.x;

    if (blk < 2048) {
        const int total = B_*1360*128;
        for (int e = blk*256 + tid; e < total; e += 2048*256) {
            int ci = e & 127;
            int t  = e >> 7;
            int sp = t % 1360;
            int b  = t / 1360;
            int yy = sp / 40, xx = sp % 40;
            int y = yy - 1, c = xx - 1;
            float v = 0.f;
            if ((unsigned)y < 32u && (unsigned)c < 32u)
                v = x[((size_t)b*128 + ci)*1024 + y*32 + c];
            __nv_bfloat16 hb = __float2bfloat16(v);
            float lov = v - __bfloat162float(hb);
            __nv_bfloat16 lb = __float2bfloat16(lov);
            g_xpad_hi[e] = *(ushort_t*)&hb;
            g_xpad_lo[e] = *(ushort_t*)&lb;
        }
    } else if (blk < 3776) {
        int e = (blk - 2048)*256 + tid;
        if (e < 3*128*128*9) {
            int kx = e % 3; int t = e / 3;
            int ky = t % 3; t /= 3;
            int ci = t % 128; t /= 128;
            int co = t % 128;
            int p  = t / 128;
            const float* w = (p == 0) ? wq : (p == 1) ? wk : wv;
            float v = w[((co*128 + ci)*3 + ky)*3 + kx];
            __nv_bfloat16 h = __float2bfloat16(v);
            float lo = v - __bfloat162float(h);
            int dst = ((ky*3 + kx)*128 + co)*128 + ci;
            g_w_hi[p][dst] = h;
            g_w_lo[p][dst] = __float2bfloat16(lo);
        }
    } else if (blk < 3840) {
        int i = (blk - 3776)*256 + tid;
        if (i < 16384) {
            float v = w2[i];
            __nv_bfloat16 h = __float2bfloat16(v);
            float lo = v - __bfloat162float(h);
            __nv_bfloat16 lb = __float2bfloat16(lo);
            g_w2_hi[i] = *(ushort_t*)&h;
            g_w2_lo[i] = *(ushort_t*)&lb;
        }
    } else {
        const int n = blk - 3840;
        for (int m = tid; m < N_; m += 256) {
            int idx = rel_index[n * N_ + m];
            float4 t = *reinterpret_cast<const float4*>(table + idx * 4);
            __nv_bfloat16 b0 = __float2bfloat16(t.x * LOG2E);
            __nv_bfloat16 b1 = __float2bfloat16(t.y * LOG2E);
            __nv_bfloat16 b2 = __float2bfloat16(t.z * LOG2E);
            __nv_bfloat16 b3 = __float2bfloat16(t.w * LOG2E);
            g_bias4[(0 * N_ + n) * N_ + m] = *(ushort_t*)&b0;
            g_bias4[(1 * N_ + n) * N_ + m] = *(ushort_t*)&b1;
            g_bias4[(2 * N_ + n) * N_ + m] = *(ushort_t*)&b2;
            g_bias4[(3 * N_ + n) * N_ + m] = *(ushort_t*)&b3;
        }
    }
}

// =====================================================================
// conv3x3 bf16x3 tensor-core GEMM: 3-buffer cp.async ring (1 sync/stage)
// =====================================================================
__global__ __launch_bounds__(256, 2) void conv_mma_kernel()
{
    __shared__ __align__(16) ushort_t a_sm[3][128*104];   // 79872 B
    __shared__ __align__(16) ushort_t b_sm[3][2*136*24];  // 19584 B

    const int sp = blockIdx.x, b = blockIdx.y, p = blockIdx.z;
    const int tid = threadIdx.x, lane = tid & 31, wid = tid >> 5;
    const int wm = wid & 1, wn = wid >> 1;
    const int r0 = sp * 4;
    const int n0 = sp * 128;

    const __nv_bfloat16* whi = g_w_hi[p];
    const __nv_bfloat16* wlo = g_w_lo[p];
    const ushort_t* xh = g_xpad_hi + (size_t)b * (1360*128);
    const ushort_t* xl = g_xpad_lo + (size_t)b * (1360*128);

    float acc[4][4][4];
#pragma unroll
    for (int mi = 0; mi < 4; mi++)
#pragma unroll
        for (int ni = 0; ni < 4; ni++)
#pragma unroll
            for (int j = 0; j < 4; j++) acc[mi][ni][j] = 0.f;

    const int m_idx = lane >> 3;
    const int row_in = lane & 7;
    int aoff[4];
#pragma unroll
    for (int mi = 0; mi < 4; mi++)
        aoff[mi] = (wm*64 + mi*16 + (lane & 15))*104 + (lane >> 4)*8;
    int boff[2];
#pragma unroll
    for (int tp = 0; tp < 2; tp++) {
        int tile = tp*2 + (m_idx >> 1);
        int n = wn*32 + tile*8 + row_in;
        int rr = n >> 5, cc = n & 31;
        boff[tp] = (rr*34 + cc)*24 + (m_idx & 1)*8;
    }

    int bsrc[3], bdst[3];
    unsigned bflag[3];
#pragma unroll
    for (int it = 0; it < 3; it++) {
        int u = tid + it*256;
        int valid = (u < 544);
        int uu = valid ? u : 0;
        int half = uu & 1;
        int idx  = uu >> 1;
        int pc = idx % 34;
        int t  = idx / 34;
        int r  = t & 3;
        int split = t >> 2;
        bsrc[it] = ((r0 + r)*40 + pc)*128 + half*8;
        bdst[it] = (split*136 + r*34 + pc)*24 + half*8;
        bflag[it] = valid | (split << 1);
    }

    auto stage = [&](int s, int bufi) {
        int ky = s >> 3, ci0 = (s & 7) << 4;
        for (int u = tid; u < 1536; u += 256) {
            int half = u & 1;
            int co   = (u >> 1) & 127;
            int sk   = u >> 8;
            int split = (sk >= 3), kx = split ? sk - 3 : sk;
            const __nv_bfloat16* src = (split ? wlo : whi)
                + ((ky*3 + kx)*128 + co)*128 + ci0 + half*8;
            cp_async16(&a_sm[bufi][co*104 + sk*16 + half*8], src);
        }
        int badd = ky*5120 + ci0;
#pragma unroll
        for (int it = 0; it < 3; it++) {
            if (bflag[it] & 1) {
                const ushort_t* base = (bflag[it] & 2) ? xl : xh;
                cp_async16(&b_sm[bufi][bdst[it]], base + bsrc[it] + badd);
            }
        }
        cp_async_commit();
    };

    stage(0, 0);
    stage(1, 1);
    for (int s = 0; s < 24; s++) {
        if (s < 23) cp_async_wait1();
        else        cp_async_wait0();
        __syncthreads();
        if (s + 2 < 24) stage(s + 2, (s + 2) % 3);

        const ushort_t* ab = a_sm[s % 3];
        const ushort_t* bb = b_sm[s % 3];
#pragma unroll
        for (int kx = 0; kx < 3; kx++) {
            unsigned bf[4][2], Af[4][4];
            {
                unsigned t4[4];
                ldmatrix_x4(t4, bb + boff[0] + kx*24);
                bf[0][0]=t4[0]; bf[0][1]=t4[1]; bf[1][0]=t4[2]; bf[1][1]=t4[3];
                ldmatrix_x4(t4, bb + boff[1] + kx*24);
                bf[2][0]=t4[0]; bf[2][1]=t4[1]; bf[3][0]=t4[2]; bf[3][1]=t4[3];
            }
#pragma unroll
            for (int mi = 0; mi < 4; mi++)
                ldmatrix_x4(Af[mi], ab + aoff[mi] + kx*16);
#pragma unroll
            for (int ni = 0; ni < 4; ni++)
#pragma unroll
                for (int mi = 0; mi < 4; mi++)
                    mma_bf16(acc[mi][ni], Af[mi], bf[ni][0], bf[ni][1]);
            unsigned bl[4][2];
            {
                unsigned t4[4];
                ldmatrix_x4(t4, bb + 136*24 + boff[0] + kx*24);
                bl[0][0]=t4[0]; bl[0][1]=t4[1]; bl[1][0]=t4[2]; bl[1][1]=t4[3];
                ldmatrix_x4(t4, bb + 136*24 + boff[1] + kx*24);
                bl[2][0]=t4[0]; bl[2][1]=t4[1]; bl[3][0]=t4[2]; bl[3][1]=t4[3];
            }
#pragma unroll
            for (int ni = 0; ni < 4; ni++)
#pragma unroll
                for (int mi = 0; mi < 4; mi++)
                    mma_bf16(acc[mi][ni], Af[mi], bl[ni][0], bl[ni][1]);
#pragma unroll
            for (int mi = 0; mi < 4; mi++)
                ldmatrix_x4(Af[mi], ab + aoff[mi] + (3 + kx)*16);
#pragma unroll
            for (int ni = 0; ni < 4; ni++)
#pragma unroll
                for (int mi = 0; mi < 4; mi++)
                    mma_bf16(acc[mi][ni], Af[mi], bf[ni][0], bf[ni][1]);
        }
    }

    float s1 = 0.f, s2 = 0.f;
    float* outb = &g_conv[p][(size_t)b * CN];
#pragma unroll
    for (int mi = 0; mi < 4; mi++) {
        int row = wm*64 + mi*16 + (lane >> 2);
#pragma unroll
        for (int ni = 0; ni < 4; ni++) {
            int col = n0 + wn*32 + ni*8 + (lane & 3)*2;
            float2 v0; v0.x = acc[mi][ni][0]; v0.y = acc[mi][ni][1];
            float2 v1; v1.x = acc[mi][ni][2]; v1.y = acc[mi][ni][3];
            *reinterpret_cast<float2*>(&outb[(size_t)row*1024 + col])     = v0;
            *reinterpret_cast<float2*>(&outb[(size_t)(row+8)*1024 + col]) = v1;
#pragma unroll
            for (int j = 0; j < 4; j++) {
                float v = acc[mi][ni][j];
                s1 += v; s2 = fmaf(v, v, s2);
            }
        }
    }
    float* red = reinterpret_cast<float*>(b_sm);
    red[tid] = s1; red[256 + tid] = s2;
    __syncthreads();
    for (int st = 128; st > 0; st >>= 1) {
        if (tid < st) { red[tid] += red[tid + st]; red[256 + tid] += red[256 + tid + st]; }
        __syncthreads();
    }
    if (tid == 0) {
        int slot = (p*16 + b)*8 + sp;
        g_part2[slot][0] = red[0];
        g_part2[slot][1] = red[256];
    }
}

// =====================================================================
// GroupNorm apply (inline finalize) + exact GELU -> operands.
// Q scaled by log2e; V emitted as single fp16.
// =====================================================================
__global__ __launch_bounds__(256) void norm_gelu_kernel(
    const float* __restrict__ gq, const float* __restrict__ bq,
    const float* __restrict__ gk, const float* __restrict__ bk,
    const float* __restrict__ gv, const float* __restrict__ bv)
{
    const int pb = blockIdx.z;
    const int p = pb >> 4, b = pb & 15;
    const int h = blockIdx.y;
    const int n0 = blockIdx.x * 64;
    const int tid = threadIdx.x;
    const int bhid = b*4 + h;

    const float* gamma = (p == 0) ? gq : (p == 1) ? gk : gv;
    const float* beta  = (p == 0) ? bq : (p == 1) ? bk : bv;

    float sa = 0.f, sb = 0.f;
#pragma unroll
    for (int i = 0; i < 8; i++) {
        sa += g_part2[pb*8 + i][0];
        sb += g_part2[pb*8 + i][1];
    }
    const float mean = sa / (float)CN;
    const float rstd = rsqrtf(sb / (float)CN - mean*mean + 1e-6f);

    __shared__ float s[32][65];
    const float* src = g_conv[p] + ((size_t)b * 128 + h * 32) * N_;

    if (p == 2) {
        for (int e = tid; e < 2048; e += 256) {
            int d = e >> 6, nn = e & 63;
            float v = src[(size_t)d * N_ + n0 + nn];
            int c = h * 32 + d;
            v = (v - mean) * rstd * gamma[c] + beta[c];
            v = 0.5f * v * (1.0f + erff(v * 0.70710678118654752f));
            __half hv = __float2half(v);
            size_t idx = ((size_t)bhid*32 + d)*1024 + n0 + nn;
            g_v16[idx] = *(ushort_t*)&hv;
        }
    } else {
        const float qscale = (p == 0) ? LOG2E : 1.0f;
        for (int e = tid; e < 2048; e += 256) {
            int d = e >> 6, nn = e & 63;
            float v = src[(size_t)d * N_ + n0 + nn];
            int c = h * 32 + d;
            v = (v - mean) * rstd * gamma[c] + beta[c];
            v = 0.5f * v * (1.0f + erff(v * 0.70710678118654752f));
            s[d][nn] = v * qscale;
        }
        __syncthreads();
        ushort_t* dhi = (p == 0) ? g_q_hi : g_k_hi;
        ushort_t* dlo = (p == 0) ? g_q_lo : g_k_lo;
        for (int e = tid; e < 2048; e += 256) {
            int nn = e >> 5, d = e & 31;
            float v = s[d][nn];
            __nv_bfloat16 hb = __float2bfloat16(v);
            float lov = v - __bfloat162float(hb);
            __nv_bfloat16 lb = __float2bfloat16(lov);
            size_t idx = ((size_t)bhid*1024 + n0 + nn)*32 + d;
            dhi[idx] = *(ushort_t*)&hb;
            dlo[idx] = *(ushort_t*)&lb;
        }
    }
}

// =====================================================================
// Attention v6: bf16x3 S + exp2 softmax + fp16 2-term PV (V single fp16)
// =====================================================================
__global__ __launch_bounds__(256, 2) void attn_mma_kernel()
{
    __shared__ __align__(16) ushort_t q_sm[2][128][40];      // 20480 B
    __shared__ __align__(16) ushort_t k_sm[2][2*64*40];      // 20480 B
    __shared__ __align__(16) ushort_t v_sm[2][32*72];        //  9216 B

    const int tid = threadIdx.x, lane = tid & 31, w = tid >> 5;
    const int qt = blockIdx.x, bh = blockIdx.y;
    const int b = bh >> 2, h = bh & 3;

    // precomputed staging pointers: 2 for K, 1 for V
    const ushort_t* ksrc[2];
    int kdst[2];
#pragma unroll
    for (int i = 0; i < 2; i++) {
        int u = tid + i*256;
        int quarter = u & 3, row = (u >> 2) & 63, split = u >> 8;
        ksrc[i] = (split ? g_k_lo : g_k_hi) + ((size_t)bh*1024 + row)*32 + quarter*8;
        kdst[i] = (split*64 + row)*40 + quarter*8;
    }
    const ushort_t* vsrc;
    int vdst;
    {
        int seg = tid & 7, d = (tid >> 3) & 31;
        vsrc = g_v16 + ((size_t)bh*32 + d)*1024 + seg*8;
        vdst = d*72 + seg*8;
    }

    auto stage_kv = [&](int kc, int bufi) {
#pragma unroll
        for (int i = 0; i < 2; i++)
            cp_async16(&k_sm[bufi][kdst[i]], ksrc[i] + kc*2048);
        cp_async16(&v_sm[bufi][vdst], vsrc + kc*64);
        cp_async_commit();
    };

    for (int u = tid; u < 1024; u += 256) {
        int quarter = u & 3, row = (u >> 2) & 127, split = u >> 9;
        const ushort_t* src = (split ? g_q_lo : g_q_hi)
            + ((size_t)bh*1024 + qt*128 + row)*32 + quarter*8;
        *reinterpret_cast<uint4*>(&q_sm[split][row][quarter*8]) =
            *reinterpret_cast<const uint4*>(src);
    }
    stage_kv(0, 0);
    __syncthreads();

    unsigned qh[2][4], ql[2][4];
#pragma unroll
    for (int kit = 0; kit < 2; kit++) {
        ldmatrix_x4(qh[kit], &q_sm[0][w*16 + (lane & 15)][kit*16 + (lane >> 4)*8]);
        ldmatrix_x4(ql[kit], &q_sm[1][w*16 + (lane & 15)][kit*16 + (lane >> 4)*8]);
    }

    const int m_idx = lane >> 3;
    const int row_in = lane & 7;
    int koff[4], voff[2];
#pragma unroll
    for (int tp = 0; tp < 4; tp++)
        koff[tp] = ((tp*2 + (m_idx >> 1))*8 + row_in)*40 + (m_idx & 1)*8;
#pragma unroll
    for (int tp = 0; tp < 2; tp++)
        voff[tp] = ((tp*2 + (m_idx >> 1))*8 + row_in)*72 + (m_idx & 1)*8;

    float O[4][4];
#pragma unroll
    for (int nd = 0; nd < 4; nd++)
#pragma unroll
        for (int j = 0; j < 4; j++) O[nd][j] = 0.f;
    float mrun0 = -INFINITY, mrun1 = -INFINITY, lrun0 = 0.f, lrun1 = 0.f;

    const int qrow0 = qt*128 + w*16 + (lane >> 2);
    const ushort_t* biasbase = g_bias4 + ((size_t)h*1024 + qrow0)*1024 + 2*(lane & 3);

    for (int kc = 0; kc < 16; kc++) {
        const int m0 = kc * 64;
        const int buf = kc & 1;
        if (kc + 1 < 16) { stage_kv(kc + 1, buf ^ 1); cp_async_wait1(); }
        else             { cp_async_wait0(); }
        __syncthreads();

        const ushort_t* kb0 = k_sm[buf];
        const ushort_t* kb1 = kb0 + 64*40;
        const ushort_t* vb0 = v_sm[buf];

        float c[8][4];
#pragma unroll
        for (int ni = 0; ni < 8; ni++)
#pragma unroll
            for (int j = 0; j < 4; j++) c[ni][j] = 0.f;

#pragma unroll
        for (int kit = 0; kit < 2; kit++) {
            unsigned kb[8][2];
#pragma unroll
            for (int tp = 0; tp < 4; tp++) {
                unsigned t4[4];
                ldmatrix_x4(t4, kb0 + koff[tp] + kit*16);
                kb[tp*2][0]=t4[0]; kb[tp*2][1]=t4[1];
                kb[tp*2+1][0]=t4[2]; kb[tp*2+1][1]=t4[3];
            }
#pragma unroll
            for (int ni = 0; ni < 8; ni++) {
                mma_bf16(c[ni], qh[kit], kb[ni][0], kb[ni][1]);
                mma_bf16(c[ni], ql[kit], kb[ni][0], kb[ni][1]);
            }
#pragma unroll
            for (int tp = 0; tp < 4; tp++) {
                unsigned t4[4];
                ldmatrix_x4(t4, kb1 + koff[tp] + kit*16);
                kb[tp*2][0]=t4[0]; kb[tp*2][1]=t4[1];
                kb[tp*2+1][0]=t4[2]; kb[tp*2+1][1]=t4[3];
            }
#pragma unroll
            for (int ni = 0; ni < 8; ni++)
                mma_bf16(c[ni], qh[kit], kb[ni][0], kb[ni][1]);
        }

        // bias (bf16, log2-domain) + online softmax via exp2
        const ushort_t* b0p = biasbase + m0;
        const ushort_t* b1p = b0p + 8*1024;
        float rm0 = -INFINITY, rm1 = -INFINITY;
#pragma unroll
        for (int ni = 0; ni < 8; ni++) {
            unsigned u0 = *reinterpret_cast<const unsigned*>(b0p + ni*8);
            unsigned u1 = *reinterpret_cast<const unsigned*>(b1p + ni*8);
            c[ni][0] += lowerf(u0); c[ni][1] += upperf(u0);
            c[ni][2] += lowerf(u1); c[ni][3] += upperf(u1);
            rm0 = fmaxf(rm0, fmaxf(c[ni][0], c[ni][1]));
            rm1 = fmaxf(rm1, fmaxf(c[ni][2], c[ni][3]));
        }
        rm0 = fmaxf(rm0, __shfl_xor_sync(0xffffffffu, rm0, 1));
        rm0 = fmaxf(rm0, __shfl_xor_sync(0xffffffffu, rm0, 2));
        rm1 = fmaxf(rm1, __shfl_xor_sync(0xffffffffu, rm1, 1));
        rm1 = fmaxf(rm1, __shfl_xor_sync(0xffffffffu, rm1, 2));
        float mnew0 = fmaxf(mrun0, rm0), mnew1 = fmaxf(mrun1, rm1);
        float corr0 = ex2(mrun0 - mnew0), corr1 = ex2(mrun1 - mnew1);
        mrun0 = mnew0; mrun1 = mnew1;
        float rs0 = 0.f, rs1 = 0.f;
#pragma unroll
        for (int ni = 0; ni < 8; ni++) {
            c[ni][0] = ex2(c[ni][0] - mnew0);
            c[ni][1] = ex2(c[ni][1] - mnew0);
            c[ni][2] = ex2(c[ni][2] - mnew1);
            c[ni][3] = ex2(c[ni][3] - mnew1);
            rs0 += c[ni][0] + c[ni][1];
            rs1 += c[ni][2] + c[ni][3];
        }
        rs0 += __shfl_xor_sync(0xffffffffu, rs0, 1);
        rs0 += __shfl_xor_sync(0xffffffffu, rs0, 2);
        rs1 += __shfl_xor_sync(0xffffffffu, rs1, 1);
        rs1 += __shfl_xor_sync(0xffffffffu, rs1, 2);
        lrun0 = lrun0 * corr0 + rs0;
        lrun1 = lrun1 * corr1 + rs1;
#pragma unroll
        for (int nd = 0; nd < 4; nd++) {
            O[nd][0] *= corr0; O[nd][1] *= corr0;
            O[nd][2] *= corr1; O[nd][3] *= corr1;
        }

        // ---- PV: fp16 2-term (ph + pl) x V_fp16 ----
#pragma unroll
        for (int t = 0; t < 4; t++) {
            int j0 = 2*t, j1 = 2*t + 1;
            unsigned ph[4], pl[4];
            ph[0] = packh(c[j0][1], c[j0][0]);
            ph[1] = packh(c[j0][3], c[j0][2]);
            ph[2] = packh(c[j1][1], c[j1][0]);
            ph[3] = packh(c[j1][3], c[j1][2]);
            pl[0] = packh(c[j0][1] - hhi(ph[0]), c[j0][0] - hlo(ph[0]));
            pl[1] = packh(c[j0][3] - hhi(ph[1]), c[j0][2] - hlo(ph[1]));
            pl[2] = packh(c[j1][1] - hhi(ph[2]), c[j1][0] - hlo(ph[2]));
            pl[3] = packh(c[j1][3] - hhi(ph[3]), c[j1][2] - hlo(ph[3]));

            unsigned vb[4][2];
#pragma unroll
            for (int tp = 0; tp < 2; tp++) {
                unsigned t4[4];
                ldmatrix_x4(t4, vb0 + voff[tp] + t*16);
                vb[tp*2][0]=t4[0]; vb[tp*2][1]=t4[1];
                vb[tp*2+1][0]=t4[2]; vb[tp*2+1][1]=t4[3];
            }
#pragma unroll
            for (int nd = 0; nd < 4; nd++) {
                mma_fp16(O[nd], ph, vb[nd][0], vb[nd][1]);
                mma_fp16(O[nd], pl, vb[nd][0], vb[nd][1]);
            }
        }
        __syncthreads();
    }

    // epilogue: bf16 hi/lo split output [b][n][c]
    float il0 = 1.f / lrun0, il1 = 1.f / lrun1;
    const size_t base0 = ((size_t)b*1024 + qrow0)*128 + h*32 + 2*(lane & 3);
    const size_t base1 = base0 + 8*128;
#pragma unroll
    for (int nd = 0; nd < 4; nd++) {
        float a0 = O[nd][0]*il0, a1 = O[nd][1]*il0;
        float b0 = O[nd][2]*il1, b1 = O[nd][3]*il1;
        unsigned h0 = packbf(a1, a0);
        unsigned l0 = packbf(a1 - upperf(h0), a0 - lowerf(h0));
        unsigned h1 = packbf(b1, b0);
        unsigned l1 = packbf(b1 - upperf(h1), b0 - lowerf(h1));
        *reinterpret_cast<unsigned*>(&g_ao_hi[base0 + nd*8]) = h0;
        *reinterpret_cast<unsigned*>(&g_ao_lo[base0 + nd*8]) = l0;
        *reinterpret_cast<unsigned*>(&g_ao_hi[base1 + nd*8]) = h1;
        *reinterpret_cast<unsigned*>(&g_ao_lo[base1 + nd*8]) = l1;
    }
}

// =====================================================================
// 1x1 conv via tensor cores (bf16x3), + bias.
// =====================================================================
__global__ __launch_bounds__(256, 2) void outconv_mma_kernel(
    const float* __restrict__ bias, float* __restrict__ out)
{
    __shared__ __align__(16) ushort_t a_sm[2][128*40];
    __shared__ __align__(16) ushort_t b_sm[2][128*40];

    const int bx = blockIdx.x, b = blockIdx.y;
    const int n0 = bx * 128;
    const int tid = threadIdx.x, lane = tid & 31, wid = tid >> 5;
    const int wm = wid & 1, wn = wid >> 1;
    const int m_idx = lane >> 3;
    const int row_in = lane & 7;

    float acc[4][4][4];
#pragma unroll
    for (int mi = 0; mi < 4; mi++)
#pragma unroll
        for (int ni = 0; ni < 4; ni++)
#pragma unroll
            for (int j = 0; j < 4; j++) acc[mi][ni][j] = 0.f;

    int aoff[4];
#pragma unroll
    for (int mi = 0; mi < 4; mi++)
        aoff[mi] = (wm*64 + mi*16 + (lane & 15))*40 + (lane >> 4)*8;
    int boff[2];
#pragma unroll
    for (int tp = 0; tp < 2; tp++) {
        int tile = tp*2 + (m_idx >> 1);
        int n = wn*32 + tile*8 + row_in;
        boff[tp] = n*40 + (m_idx & 1)*8;
    }

    auto stage = [&](int ck, int bufi) {
        int c0 = ck * 16;
        for (int u = tid; u < 512; u += 256) {
            int half = u & 1, co = (u >> 1) & 127, split = u >> 8;
            const ushort_t* src = (split ? g_w2_lo : g_w2_hi) + co*128 + c0 + half*8;
            cp_async16(&a_sm[bufi][co*40 + split*16 + half*8], src);
        }
        for (int u = tid; u < 512; u += 256) {
            int half = u & 1, n = (u >> 1) & 127, split = u >> 8;
            const ushort_t* src = (split ? g_ao_lo : g_ao_hi)
                + ((size_t)b*1024 + n0 + n)*128 + c0 + half*8;
            cp_async16(&b_sm[bufi][n*40 + split*16 + half*8], src);
        }
        cp_async_commit();
    };

    stage(0, 0);
    for (int ck = 0; ck < 8; ck++) {
        const int buf = ck & 1;
        if (ck + 1 < 8) { stage(ck + 1, buf ^ 1); cp_async_wait1(); }
        else            { cp_async_wait0(); }
        __syncthreads();

        const ushort_t* ab = a_sm[buf];
        const ushort_t* bb = b_sm[buf];

        unsigned Ah[4][4], bf[4][2], bl[4][2];
#pragma unroll
        for (int mi = 0; mi < 4; mi++)
            ldmatrix_x4(Ah[mi], ab + aoff[mi]);
        {
            unsigned t4[4];
            ldmatrix_x4(t4, bb + boff[0]);
            bf[0][0]=t4[0]; bf[0][1]=t4[1]; bf[1][0]=t4[2]; bf[1][1]=t4[3];
            ldmatrix_x4(t4, bb + boff[1]);
            bf[2][0]=t4[0]; bf[2][1]=t4[1]; bf[3][0]=t4[2]; bf[3][1]=t4[3];
            ldmatrix_x4(t4, bb + boff[0] + 16);
            bl[0][0]=t4[0]; bl[0][1]=t4[1]; bl[1][0]=t4[2]; bl[1][1]=t4[3];
            ldmatrix_x4(t4, bb + boff[1] + 16);
            bl[2][0]=t4[0]; bl[2][1]=t4[1]; bl[3][0]=t4[2]; bl[3][1]=t4[3];
        }
#pragma unroll
        for (int ni = 0; ni < 4; ni++)
#pragma unroll
            for (int mi = 0; mi < 4; mi++) {
                mma_bf16(acc[mi][ni], Ah[mi], bf[ni][0], bf[ni][1]);
                mma_bf16(acc[mi][ni], Ah[mi], bl[ni][0], bl[ni][1]);
            }
#pragma unroll
        for (int mi = 0; mi < 4; mi++)
            ldmatrix_x4(Ah[mi], ab + aoff[mi] + 16);
#pragma unroll
        for (int ni = 0; ni < 4; ni++)
#pragma unroll
            for (int mi = 0; mi < 4; mi++)
                mma_bf16(acc[mi][ni], Ah[mi], bf[ni][0], bf[ni][1]);
        __syncthreads();
    }

#pragma unroll
    for (int mi = 0; mi < 4; mi++) {
        int row = wm*64 + mi*16 + (lane >> 2);
        float bv0 = bias[row], bv1 = bias[row + 8];
#pragma unroll
        for (int ni = 0; ni < 4; ni++) {
            int col = n0 + wn*32 + ni*8 + (lane & 3)*2;
            float2 v0; v0.x = acc[mi][ni][0] + bv0; v0.y = acc[mi][ni][1] + bv0;
            float2 v1; v1.x = acc[mi][ni][2] + bv1; v1.y = acc[mi][ni][3] + bv1;
            *reinterpret_cast<float2*>(&out[((size_t)b*128 + row)*1024 + col])     = v0;
            *reinterpret_cast<float2*>(&out[((size_t)b*128 + row + 8)*1024 + col]) = v1;
        }
    }
}

// =====================================================================
extern "C" void kernel_launch(void* const* d_in, const int* in_sizes, int n_in,
                              void* d_out, int out_size)
{
    const float* x      = (const float*)d_in[0];
    const float* wq     = (const float*)d_in[1];
    const float* gq     = (const float*)d_in[2];
    const float* bq     = (const float*)d_in[3];
    const float* wk     = (const float*)d_in[4];
    const float* gk     = (const float*)d_in[5];
    const float* bk     = (const float*)d_in[6];
    const float* wv     = (const float*)d_in[7];
    const float* gv     = (const float*)d_in[8];
    const float* bv     = (const float*)d_in[9];
    const float* table  = (const float*)d_in[10];
    const int*   relidx = (const int*)  d_in[11];
    const float* out_w  = (const float*)d_in[12];
    const float* out_b  = (const float*)d_in[13];
    float* out = (float*)d_out;

    prep_all_kernel<<<4864, 256>>>(x, wq, wk, wv, out_w, table, relidx); // 0
    conv_mma_kernel<<<dim3(8, 16, 3), 256>>>();                          // 1
    norm_gelu_kernel<<<dim3(16, 4, 48), 256>>>(gq, bq, gk, bk, gv, bv);  // 2
    attn_mma_kernel<<<dim3(8, 64), 256>>>();                             // 3  <- profiled
    outconv_mma_kernel<<<dim3(8, 16), 256>>>(out_b, out);                // 4
}

// round 14
// speedup vs baseline: 1.5918x; 1.5918x over previous
#include <cuda_runtime.h>
#include <cuda_bf16.h>
#include <math.h>

#define B_   16
#define C_   128
#define N_   1024
#define H_   4
#define D_   32
#define CN   (C_*N_)
#define LOG2E 1.4426950408889634f

typedef unsigned short ushort_t;

// ---------------- scratch (device globals; no allocations) ----------------
__device__ float g_conv[3][B_*CN];        // conv outputs, [p][b][c][n]
__device__ float g_part2[384][2];         // conv-block partial sums
__device__ ushort_t g_bias4[H_*N_*N_];    // [h][n][m]  (bf16 bits, pre-scaled by log2e)

// padded input, transposed: [b][sp_pad(34*40)][ci(128)], hi/lo bf16 bits
__device__ __align__(16) ushort_t g_xpad_hi[B_*34*40*C_];
__device__ __align__(16) ushort_t g_xpad_lo[B_*34*40*C_];
// weights: [p][((ky*3+kx)*128+co)*128+ci]
__device__ __align__(16) __nv_bfloat16 g_w_hi[3][9*128*128];
__device__ __align__(16) __nv_bfloat16 g_w_lo[3][9*128*128];
// out_w split: [co][ci]
__device__ __align__(16) ushort_t g_w2_hi[128*128];
__device__ __align__(16) ushort_t g_w2_lo[128*128];

// attention operands (bf16 bits, hi/lo split).  Q pre-scaled by log2e.
__device__ __align__(16) ushort_t g_q_hi[64*N_*D_];   // [bh][n][d]
__device__ __align__(16) ushort_t g_q_lo[64*N_*D_];
__device__ __align__(16) ushort_t g_k_hi[64*N_*D_];   // [bh][n][d]
__device__ __align__(16) ushort_t g_k_lo[64*N_*D_];
__device__ __align__(16) ushort_t g_v_hi[64*D_*N_];   // [bh][d][n]  (transposed)
__device__ __align__(16) ushort_t g_v_lo[64*D_*N_];
// attention output, bf16 hi/lo: [b][n][c]
__device__ __align__(16) ushort_t g_ao_hi[B_*N_*C_];
__device__ __align__(16) ushort_t g_ao_lo[B_*N_*C_];

// =====================================================================
// helpers
// =====================================================================
__device__ __forceinline__ void mma_bf16(float* d, const unsigned* A,
                                         unsigned b0, unsigned b1)
{
    asm volatile(
        "mma.sync.aligned.m16n8k16.row.col.f32.bf16.bf16.f32 "
        "{%0,%1,%2,%3},{%4,%5,%6,%7},{%8,%9},{%0,%1,%2,%3};"
        : "+f"(d[0]), "+f"(d[1]), "+f"(d[2]), "+f"(d[3])
        : "r"(A[0]), "r"(A[1]), "r"(A[2]), "r"(A[3]), "r"(b0), "r"(b1));
}

__device__ __forceinline__ void ldmatrix_x4(unsigned* r, const ushort_t* p)
{
    unsigned addr = (unsigned)__cvta_generic_to_shared((void*)p);
    asm volatile("ldmatrix.sync.aligned.m8n8.x4.shared.b16 {%0,%1,%2,%3}, [%4];"
        : "=r"(r[0]), "=r"(r[1]), "=r"(r[2]), "=r"(r[3]) : "r"(addr));
}

__device__ __forceinline__ void cp_async16(void* smem, const void* gmem)
{
    unsigned s = (unsigned)__cvta_generic_to_shared(smem);
    asm volatile("cp.async.cg.shared.global [%0], [%1], 16;" :: "r"(s), "l"(gmem));
}
__device__ __forceinline__ void cp_async_commit(){ asm volatile("cp.async.commit_group;"); }
__device__ __forceinline__ void cp_async_wait0(){ asm volatile("cp.async.wait_group 0;" ::: "memory"); }
__device__ __forceinline__ void cp_async_wait1(){ asm volatile("cp.async.wait_group 1;" ::: "memory"); }

__device__ __forceinline__ unsigned packbf(float hi_elem, float lo_elem)
{
    unsigned d;
    asm("cvt.rn.bf16x2.f32 %0, %1, %2;" : "=r"(d) : "f"(hi_elem), "f"(lo_elem));
    return d;
}
__device__ __forceinline__ float upperf(unsigned u){ return __uint_as_float(u & 0xffff0000u); }
__device__ __forceinline__ float lowerf(unsigned u){ return __uint_as_float(u << 16); }
__device__ __forceinline__ float ex2(float x)
{
    float r;
    asm("ex2.approx.ftz.f32 %0, %1;" : "=f"(r) : "f"(x));
    return r;
}

// =====================================================================
// prep_all
// =====================================================================
__global__ __launch_bounds__(256) void prep_all_kernel(
    const float* __restrict__ x,
    const float* __restrict__ wq, const float* __restrict__ wk,
    const float* __restrict__ wv, const float* __restrict__ w2,
    const float* __restrict__ table, const int* __restrict__ rel_index)
{
    const int blk = blockIdx.x;
    const int tid = threadIdx.x;

    if (blk < 2048) {
        const int total = B_*1360*128;
        for (int e = blk*256 + tid; e < total; e += 2048*256) {
            int ci = e & 127;
            int t  = e >> 7;
            int sp = t % 1360;
            int b  = t / 1360;
            int yy = sp / 40, xx = sp % 40;
            int y = yy - 1, c = xx - 1;
            float v = 0.f;
            if ((unsigned)y < 32u && (unsigned)c < 32u)
                v = x[((size_t)b*128 + ci)*1024 + y*32 + c];
            __nv_bfloat16 hb = __float2bfloat16(v);
            float lov = v - __bfloat162float(hb);
            __nv_bfloat16 lb = __float2bfloat16(lov);
            g_xpad_hi[e] = *(ushort_t*)&hb;
            g_xpad_lo[e] = *(ushort_t*)&lb;
        }
    } else if (blk < 3776) {
        int e = (blk - 2048)*256 + tid;
        if (e < 3*128*128*9) {
            int kx = e % 3; int t = e / 3;
            int ky = t % 3; t /= 3;
            int ci = t % 128; t /= 128;
            int co = t % 128;
            int p  = t / 128;
            const float* w = (p == 0) ? wq : (p == 1) ? wk : wv;
            float v = w[((co*128 + ci)*3 + ky)*3 + kx];
            __nv_bfloat16 h = __float2bfloat16(v);
            float lo = v - __bfloat162float(h);
            int dst = ((ky*3 + kx)*128 + co)*128 + ci;
            g_w_hi[p][dst] = h;
            g_w_lo[p][dst] = __float2bfloat16(lo);
        }
    } else if (blk < 3840) {
        int i = (blk - 3776)*256 + tid;
        if (i < 16384) {
            float v = w2[i];
            __nv_bfloat16 h = __float2bfloat16(v);
            float lo = v - __bfloat162float(h);
            __nv_bfloat16 lb = __float2bfloat16(lo);
            g_w2_hi[i] = *(ushort_t*)&h;
            g_w2_lo[i] = *(ushort_t*)&lb;
        }
    } else {
        const int n = blk - 3840;
        for (int m = tid; m < N_; m += 256) {
            int idx = rel_index[n * N_ + m];
            float4 t = *reinterpret_cast<const float4*>(table + idx * 4);
            // pre-scale by log2e for exp2-domain softmax
            __nv_bfloat16 b0 = __float2bfloat16(t.x * LOG2E);
            __nv_bfloat16 b1 = __float2bfloat16(t.y * LOG2E);
            __nv_bfloat16 b2 = __float2bfloat16(t.z * LOG2E);
            __nv_bfloat16 b3 = __float2bfloat16(t.w * LOG2E);
            g_bias4[(0 * N_ + n) * N_ + m] = *(ushort_t*)&b0;
            g_bias4[(1 * N_ + n) * N_ + m] = *(ushort_t*)&b1;
            g_bias4[(2 * N_ + n) * N_ + m] = *(ushort_t*)&b2;
            g_bias4[(3 * N_ + n) * N_ + m] = *(ushort_t*)&b3;
        }
    }
}

// =====================================================================
// conv3x3 as bf16x3 tensor-core GEMM (2-buffer cp.async pipeline,
// strength-reduced staging, fused GN partials) — R11 known-good
// =====================================================================
__global__ __launch_bounds__(256, 2) void conv_mma_kernel()
{
    __shared__ __align__(16) ushort_t a_sm[2][128*104];   // 53248 B
    __shared__ __align__(16) ushort_t b_sm[2][2*136*24];  // 26112 B

    const int sp = blockIdx.x, b = blockIdx.y, p = blockIdx.z;
    const int tid = threadIdx.x, lane = tid & 31, wid = tid >> 5;
    const int wm = wid & 1, wn = wid >> 1;
    const int r0 = sp * 4;
    const int n0 = sp * 128;

    const __nv_bfloat16* whi = g_w_hi[p];
    const __nv_bfloat16* wlo = g_w_lo[p];
    const ushort_t* xh = g_xpad_hi + (size_t)b * (1360*128);
    const ushort_t* xl = g_xpad_lo + (size_t)b * (1360*128);

    float acc[4][4][4];
#pragma unroll
    for (int mi = 0; mi < 4; mi++)
#pragma unroll
        for (int ni = 0; ni < 4; ni++)
#pragma unroll
            for (int j = 0; j < 4; j++) acc[mi][ni][j] = 0.f;

    const int m_idx = lane >> 3;
    const int row_in = lane & 7;
    int aoff[4];
#pragma unroll
    for (int mi = 0; mi < 4; mi++)
        aoff[mi] = (wm*64 + mi*16 + (lane & 15))*104 + (lane >> 4)*8;
    int boff[2];
#pragma unroll
    for (int tp = 0; tp < 2; tp++) {
        int tile = tp*2 + (m_idx >> 1);
        int n = wn*32 + tile*8 + row_in;
        int rr = n >> 5, cc = n & 31;
        boff[tp] = (rr*34 + cc)*24 + (m_idx & 1)*8;
    }

    int bsrc[3], bdst[3];
    unsigned bflag[3];
#pragma unroll
    for (int it = 0; it < 3; it++) {
        int u = tid + it*256;
        int valid = (u < 544);
        int uu = valid ? u : 0;
        int half = uu & 1;
        int idx  = uu >> 1;
        int pc = idx % 34;
        int t  = idx / 34;
        int r  = t & 3;
        int split = t >> 2;
        bsrc[it] = ((r0 + r)*40 + pc)*128 + half*8;
        bdst[it] = (split*136 + r*34 + pc)*24 + half*8;
        bflag[it] = valid | (split << 1);
    }

    auto stage = [&](int s, int bufi) {
        int ky = s >> 3, ci0 = (s & 7) << 4;
        for (int u = tid; u < 1536; u += 256) {
            int half = u & 1;
            int co   = (u >> 1) & 127;
            int sk   = u >> 8;
            int split = (sk >= 3), kx = split ? sk - 3 : sk;
            const __nv_bfloat16* src = (split ? wlo : whi)
                + ((ky*3 + kx)*128 + co)*128 + ci0 + half*8;
            cp_async16(&a_sm[bufi][co*104 + sk*16 + half*8], src);
        }
        int badd = ky*5120 + ci0;
#pragma unroll
        for (int it = 0; it < 3; it++) {
            if (bflag[it] & 1) {
                const ushort_t* base = (bflag[it] & 2) ? xl : xh;
                cp_async16(&b_sm[bufi][bdst[it]], base + bsrc[it] + badd);
            }
        }
        cp_async_commit();
    };

    stage(0, 0);
    for (int s = 0; s < 24; s++) {
        const int buf = s & 1;
        if (s + 1 < 24) { stage(s + 1, buf ^ 1); cp_async_wait1(); }
        else            { cp_async_wait0(); }
        __syncthreads();

        const ushort_t* ab = a_sm[buf];
        const ushort_t* bb = b_sm[buf];
#pragma unroll
        for (int kx = 0; kx < 3; kx++) {
            unsigned bf[4][2], Af[4][4];
            {
                unsigned t4[4];
                ldmatrix_x4(t4, bb + boff[0] + kx*24);
                bf[0][0]=t4[0]; bf[0][1]=t4[1]; bf[1][0]=t4[2]; bf[1][1]=t4[3];
                ldmatrix_x4(t4, bb + boff[1] + kx*24);
                bf[2][0]=t4[0]; bf[2][1]=t4[1]; bf[3][0]=t4[2]; bf[3][1]=t4[3];
            }
#pragma unroll
            for (int mi = 0; mi < 4; mi++)
                ldmatrix_x4(Af[mi], ab + aoff[mi] + kx*16);
#pragma unroll
            for (int ni = 0; ni < 4; ni++)
#pragma unroll
                for (int mi = 0; mi < 4; mi++)
                    mma_bf16(acc[mi][ni], Af[mi], bf[ni][0], bf[ni][1]);
            unsigned bl[4][2];
            {
                unsigned t4[4];
                ldmatrix_x4(t4, bb + 136*24 + boff[0] + kx*24);
                bl[0][0]=t4[0]; bl[0][1]=t4[1]; bl[1][0]=t4[2]; bl[1][1]=t4[3];
                ldmatrix_x4(t4, bb + 136*24 + boff[1] + kx*24);
                bl[2][0]=t4[0]; bl[2][1]=t4[1]; bl[3][0]=t4[2]; bl[3][1]=t4[3];
            }
#pragma unroll
            for (int ni = 0; ni < 4; ni++)
#pragma unroll
                for (int mi = 0; mi < 4; mi++)
                    mma_bf16(acc[mi][ni], Af[mi], bl[ni][0], bl[ni][1]);
#pragma unroll
            for (int mi = 0; mi < 4; mi++)
                ldmatrix_x4(Af[mi], ab + aoff[mi] + (3 + kx)*16);
#pragma unroll
            for (int ni = 0; ni < 4; ni++)
#pragma unroll
                for (int mi = 0; mi < 4; mi++)
                    mma_bf16(acc[mi][ni], Af[mi], bf[ni][0], bf[ni][1]);
        }
        __syncthreads();
    }

    float s1 = 0.f, s2 = 0.f;
    float* outb = &g_conv[p][(size_t)b * CN];
#pragma unroll
    for (int mi = 0; mi < 4; mi++) {
        int row = wm*64 + mi*16 + (lane >> 2);
#pragma unroll
        for (int ni = 0; ni < 4; ni++) {
            int col = n0 + wn*32 + ni*8 + (lane & 3)*2;
            float2 v0; v0.x = acc[mi][ni][0]; v0.y = acc[mi][ni][1];
            float2 v1; v1.x = acc[mi][ni][2]; v1.y = acc[mi][ni][3];
            *reinterpret_cast<float2*>(&outb[(size_t)row*1024 + col])     = v0;
            *reinterpret_cast<float2*>(&outb[(size_t)(row+8)*1024 + col]) = v1;
#pragma unroll
            for (int j = 0; j < 4; j++) {
                float v = acc[mi][ni][j];
                s1 += v; s2 = fmaf(v, v, s2);
            }
        }
    }
    float* red = reinterpret_cast<float*>(b_sm);
    red[tid] = s1; red[256 + tid] = s2;
    __syncthreads();
    for (int st = 128; st > 0; st >>= 1) {
        if (tid < st) { red[tid] += red[tid + st]; red[256 + tid] += red[256 + tid + st]; }
        __syncthreads();
    }
    if (tid == 0) {
        int slot = (p*16 + b)*8 + sp;
        g_part2[slot][0] = red[0];
        g_part2[slot][1] = red[256];
    }
}

// =====================================================================
// GroupNorm apply (inline finalize) + exact GELU -> bf16 hi/lo operands
// =====================================================================
__global__ __launch_bounds__(256) void norm_gelu_kernel(
    const float* __restrict__ gq, const float* __restrict__ bq,
    const float* __restrict__ gk, const float* __restrict__ bk,
    const float* __restrict__ gv, const float* __restrict__ bv)
{
    const int pb = blockIdx.z;
    const int p = pb >> 4, b = pb & 15;
    const int h = blockIdx.y;
    const int n0 = blockIdx.x * 64;
    const int tid = threadIdx.x;
    const int bhid = b*4 + h;

    const float* gamma = (p == 0) ? gq : (p == 1) ? gk : gv;
    const float* beta  = (p == 0) ? bq : (p == 1) ? bk : bv;

    float sa = 0.f, sb = 0.f;
#pragma unroll
    for (int i = 0; i < 8; i++) {
        sa += g_part2[pb*8 + i][0];
        sb += g_part2[pb*8 + i][1];
    }
    const float mean = sa / (float)CN;
    const float rstd = rsqrtf(sb / (float)CN - mean*mean + 1e-6f);

    __shared__ float s[32][65];
    const float* src = g_conv[p] + ((size_t)b * 128 + h * 32) * N_;

    if (p == 2) {
        for (int e = tid; e < 2048; e += 256) {
            int d = e >> 6, nn = e & 63;
            float v = src[(size_t)d * N_ + n0 + nn];
            int c = h * 32 + d;
            v = (v - mean) * rstd * gamma[c] + beta[c];
            v = 0.5f * v * (1.0f + erff(v * 0.70710678118654752f));
            __nv_bfloat16 hb = __float2bfloat16(v);
            float lov = v - __bfloat162float(hb);
            __nv_bfloat16 lb = __float2bfloat16(lov);
            size_t idx = ((size_t)bhid*32 + d)*1024 + n0 + nn;
            g_v_hi[idx] = *(ushort_t*)&hb;
            g_v_lo[idx] = *(ushort_t*)&lb;
        }
    } else {
        const float qscale = (p == 0) ? LOG2E : 1.0f;
        for (int e = tid; e < 2048; e += 256) {
            int d = e >> 6, nn = e & 63;
            float v = src[(size_t)d * N_ + n0 + nn];
            int c = h * 32 + d;
            v = (v - mean) * rstd * gamma[c] + beta[c];
            v = 0.5f * v * (1.0f + erff(v * 0.70710678118654752f));
            s[d][nn] = v * qscale;
        }
        __syncthreads();
        ushort_t* dhi = (p == 0) ? g_q_hi : g_k_hi;
        ushort_t* dlo = (p == 0) ? g_q_lo : g_k_lo;
        for (int e = tid; e < 2048; e += 256) {
            int nn = e >> 5, d = e & 31;
            float v = s[d][nn];
            __nv_bfloat16 hb = __float2bfloat16(v);
            float lov = v - __bfloat162float(hb);
            __nv_bfloat16 lb = __float2bfloat16(lov);
            size_t idx = ((size_t)bhid*1024 + n0 + nn)*32 + d;
            dhi[idx] = *(ushort_t*)&hb;
            dlo[idx] = *(ushort_t*)&lb;
        }
    }
}

// =====================================================================
// Attention v5 (R11 known-good): 8 warps x 16 q-rows, bf16x3 S,
// strength-reduced KV staging, exp2 softmax, bf16x3 PV.
// =====================================================================
__global__ __launch_bounds__(256, 2) void attn_mma_kernel()
{
    __shared__ __align__(16) ushort_t q_sm[2][128][40];      // 20480 B
    __shared__ __align__(16) ushort_t k_sm[2][2*64*40];      // 20480 B
    __shared__ __align__(16) ushort_t v_sm[2][2*32*72];      // 18432 B

    const int tid = threadIdx.x, lane = tid & 31, w = tid >> 5;
    const int qt = blockIdx.x, bh = blockIdx.y;
    const int b = bh >> 2, h = bh & 3;

    const ushort_t* ksrc[2];
    const ushort_t* vsrc[2];
    int kdst[2], vdst[2];
#pragma unroll
    for (int i = 0; i < 2; i++) {
        int u = tid + i*256;
        {
            int quarter = u & 3, row = (u >> 2) & 63, split = u >> 8;
            ksrc[i] = (split ? g_k_lo : g_k_hi) + ((size_t)bh*1024 + row)*32 + quarter*8;
            kdst[i] = (split*64 + row)*40 + quarter*8;
        }
        {
            int seg = u & 7, d = (u >> 3) & 31, split = u >> 8;
            vsrc[i] = (split ? g_v_lo : g_v_hi) + ((size_t)bh*32 + d)*1024 + seg*8;
            vdst[i] = (split*32 + d)*72 + seg*8;
        }
    }

    auto stage_kv = [&](int kc, int bufi) {
#pragma unroll
        for (int i = 0; i < 2; i++)
            cp_async16(&k_sm[bufi][kdst[i]], ksrc[i] + kc*2048);
#pragma unroll
        for (int i = 0; i < 2; i++)
            cp_async16(&v_sm[bufi][vdst[i]], vsrc[i] + kc*64);
        cp_async_commit();
    };

    for (int u = tid; u < 1024; u += 256) {
        int quarter = u & 3, row = (u >> 2) & 127, split = u >> 9;
        const ushort_t* src = (split ? g_q_lo : g_q_hi)
            + ((size_t)bh*1024 + qt*128 + row)*32 + quarter*8;
        *reinterpret_cast<uint4*>(&q_sm[split][row][quarter*8]) =
            *reinterpret_cast<const uint4*>(src);
    }
    stage_kv(0, 0);
    __syncthreads();

    unsigned qh[2][4], ql[2][4];
#pragma unroll
    for (int kit = 0; kit < 2; kit++) {
        ldmatrix_x4(qh[kit], &q_sm[0][w*16 + (lane & 15)][kit*16 + (lane >> 4)*8]);
        ldmatrix_x4(ql[kit], &q_sm[1][w*16 + (lane & 15)][kit*16 + (lane >> 4)*8]);
    }

    const int m_idx = lane >> 3;
    const int row_in = lane & 7;
    int koff[4], voff[2];
#pragma unroll
    for (int tp = 0; tp < 4; tp++)
        koff[tp] = ((tp*2 + (m_idx >> 1))*8 + row_in)*40 + (m_idx & 1)*8;
#pragma unroll
    for (int tp = 0; tp < 2; tp++)
        voff[tp] = ((tp*2 + (m_idx >> 1))*8 + row_in)*72 + (m_idx & 1)*8;

    float O[4][4];
#pragma unroll
    for (int nd = 0; nd < 4; nd++)
#pragma unroll
        for (int j = 0; j < 4; j++) O[nd][j] = 0.f;
    float mrun0 = -INFINITY, mrun1 = -INFINITY, lrun0 = 0.f, lrun1 = 0.f;

    const int qrow0 = qt*128 + w*16 + (lane >> 2);
    const ushort_t* biasbase = g_bias4 + ((size_t)h*1024 + qrow0)*1024 + 2*(lane & 3);

    for (int kc = 0; kc < 16; kc++) {
        const int m0 = kc * 64;
        const int buf = kc & 1;
        if (kc + 1 < 16) { stage_kv(kc + 1, buf ^ 1); cp_async_wait1(); }
        else             { cp_async_wait0(); }
        __syncthreads();

        const ushort_t* kb0 = k_sm[buf];
        const ushort_t* kb1 = kb0 + 64*40;
        const ushort_t* vb0 = v_sm[buf];
        const ushort_t* vb1 = vb0 + 32*72;

        float c[8][4];
#pragma unroll
        for (int ni = 0; ni < 8; ni++)
#pragma unroll
            for (int j = 0; j < 4; j++) c[ni][j] = 0.f;

#pragma unroll
        for (int kit = 0; kit < 2; kit++) {
            unsigned kb[8][2];
#pragma unroll
            for (int tp = 0; tp < 4; tp++) {
                unsigned t4[4];
                ldmatrix_x4(t4, kb0 + koff[tp] + kit*16);
                kb[tp*2][0]=t4[0]; kb[tp*2][1]=t4[1];
                kb[tp*2+1][0]=t4[2]; kb[tp*2+1][1]=t4[3];
            }
#pragma unroll
            for (int ni = 0; ni < 8; ni++) {
                mma_bf16(c[ni], qh[kit], kb[ni][0], kb[ni][1]);
                mma_bf16(c[ni], ql[kit], kb[ni][0], kb[ni][1]);
            }
#pragma unroll
            for (int tp = 0; tp < 4; tp++) {
                unsigned t4[4];
                ldmatrix_x4(t4, kb1 + koff[tp] + kit*16);
                kb[tp*2][0]=t4[0]; kb[tp*2][1]=t4[1];
                kb[tp*2+1][0]=t4[2]; kb[tp*2+1][1]=t4[3];
            }
#pragma unroll
            for (int ni = 0; ni < 8; ni++)
                mma_bf16(c[ni], qh[kit], kb[ni][0], kb[ni][1]);
        }

        // bias (bf16, log2-domain) + online softmax via exp2
        const ushort_t* b0p = biasbase + m0;
        const ushort_t* b1p = b0p + 8*1024;
        float rm0 = -INFINITY, rm1 = -INFINITY;
#pragma unroll
        for (int ni = 0; ni < 8; ni++) {
            unsigned u0 = *reinterpret_cast<const unsigned*>(b0p + ni*8);
            unsigned u1 = *reinterpret_cast<const unsigned*>(b1p + ni*8);
            c[ni][0] += lowerf(u0); c[ni][1] += upperf(u0);
            c[ni][2] += lowerf(u1); c[ni][3] += upperf(u1);
            rm0 = fmaxf(rm0, fmaxf(c[ni][0], c[ni][1]));
            rm1 = fmaxf(rm1, fmaxf(c[ni][2], c[ni][3]));
        }
        rm0 = fmaxf(rm0, __shfl_xor_sync(0xffffffffu, rm0, 1));
        rm0 = fmaxf(rm0, __shfl_xor_sync(0xffffffffu, rm0, 2));
        rm1 = fmaxf(rm1, __shfl_xor_sync(0xffffffffu, rm1, 1));
        rm1 = fmaxf(rm1, __shfl_xor_sync(0xffffffffu, rm1, 2));
        float mnew0 = fmaxf(mrun0, rm0), mnew1 = fmaxf(mrun1, rm1);
        float corr0 = ex2(mrun0 - mnew0), corr1 = ex2(mrun1 - mnew1);
        mrun0 = mnew0; mrun1 = mnew1;
        float rs0 = 0.f, rs1 = 0.f;
#pragma unroll
        for (int ni = 0; ni < 8; ni++) {
            c[ni][0] = ex2(c[ni][0] - mnew0);
            c[ni][1] = ex2(c[ni][1] - mnew0);
            c[ni][2] = ex2(c[ni][2] - mnew1);
            c[ni][3] = ex2(c[ni][3] - mnew1);
            rs0 += c[ni][0] + c[ni][1];
            rs1 += c[ni][2] + c[ni][3];
        }
        rs0 += __shfl_xor_sync(0xffffffffu, rs0, 1);
        rs0 += __shfl_xor_sync(0xffffffffu, rs0, 2);
        rs1 += __shfl_xor_sync(0xffffffffu, rs1, 1);
        rs1 += __shfl_xor_sync(0xffffffffu, rs1, 2);
        lrun0 = lrun0 * corr0 + rs0;
        lrun1 = lrun1 * corr1 + rs1;
#pragma unroll
        for (int nd = 0; nd < 4; nd++) {
            O[nd][0] *= corr0; O[nd][1] *= corr0;
            O[nd][2] *= corr1; O[nd][3] *= corr1;
        }

#pragma unroll
        for (int t = 0; t < 4; t++) {
            int j0 = 2*t, j1 = 2*t + 1;
            unsigned ph[4], pl[4];
            ph[0] = packbf(c[j0][1], c[j0][0]);
            ph[1] = packbf(c[j0][3], c[j0][2]);
            ph[2] = packbf(c[j1][1], c[j1][0]);
            ph[3] = packbf(c[j1][3], c[j1][2]);
            pl[0] = packbf(c[j0][1] - upperf(ph[0]), c[j0][0] - lowerf(ph[0]));
            pl[1] = packbf(c[j0][3] - upperf(ph[1]), c[j0][2] - lowerf(ph[1]));
            pl[2] = packbf(c[j1][1] - upperf(ph[2]), c[j1][0] - lowerf(ph[2]));
            pl[3] = packbf(c[j1][3] - upperf(ph[3]), c[j1][2] - lowerf(ph[3]));

            unsigned vb[4][2];
#pragma unroll
            for (int tp = 0; tp < 2; tp++) {
                unsigned t4[4];
                ldmatrix_x4(t4, vb0 + voff[tp] + t*16);
                vb[tp*2][0]=t4[0]; vb[tp*2][1]=t4[1];
                vb[tp*2+1][0]=t4[2]; vb[tp*2+1][1]=t4[3];
            }
#pragma unroll
            for (int nd = 0; nd < 4; nd++) {
                mma_bf16(O[nd], ph, vb[nd][0], vb[nd][1]);
                mma_bf16(O[nd], pl, vb[nd][0], vb[nd][1]);
            }
#pragma unroll
            for (int tp = 0; tp < 2; tp++) {
                unsigned t4[4];
                ldmatrix_x4(t4, vb1 + voff[tp] + t*16);
                vb[tp*2][0]=t4[0]; vb[tp*2][1]=t4[1];
                vb[tp*2+1][0]=t4[2]; vb[tp*2+1][1]=t4[3];
            }
#pragma unroll
            for (int nd = 0; nd < 4; nd++)
                mma_bf16(O[nd], ph, vb[nd][0], vb[nd][1]);
        }
        __syncthreads();
    }

    // epilogue: bf16 hi/lo split output [b][n][c]
    float il0 = 1.f / lrun0, il1 = 1.f / lrun1;
    const size_t base0 = ((size_t)b*1024 + qrow0)*128 + h*32 + 2*(lane & 3);
    const size_t base1 = base0 + 8*128;
#pragma unroll
    for (int nd = 0; nd < 4; nd++) {
        float a0 = O[nd][0]*il0, a1 = O[nd][1]*il0;
        float b0 = O[nd][2]*il1, b1 = O[nd][3]*il1;
        unsigned h0 = packbf(a1, a0);
        unsigned l0 = packbf(a1 - upperf(h0), a0 - lowerf(h0));
        unsigned h1 = packbf(b1, b0);
        unsigned l1 = packbf(b1 - upperf(h1), b0 - lowerf(h1));
        *reinterpret_cast<unsigned*>(&g_ao_hi[base0 + nd*8]) = h0;
        *reinterpret_cast<unsigned*>(&g_ao_lo[base0 + nd*8]) = l0;
        *reinterpret_cast<unsigned*>(&g_ao_hi[base1 + nd*8]) = h1;
        *reinterpret_cast<unsigned*>(&g_ao_lo[base1 + nd*8]) = l1;
    }
}

// =====================================================================
// 1x1 conv via tensor cores (bf16x3), + bias.
// =====================================================================
__global__ __launch_bounds__(256, 2) void outconv_mma_kernel(
    const float* __restrict__ bias, float* __restrict__ out)
{
    __shared__ __align__(16) ushort_t a_sm[2][128*40];
    __shared__ __align__(16) ushort_t b_sm[2][128*40];

    const int bx = blockIdx.x, b = blockIdx.y;
    const int n0 = bx * 128;
    const int tid = threadIdx.x, lane = tid & 31, wid = tid >> 5;
    const int wm = wid & 1, wn = wid >> 1;
    const int m_idx = lane >> 3;
    const int row_in = lane & 7;

    float acc[4][4][4];
#pragma unroll
    for (int mi = 0; mi < 4; mi++)
#pragma unroll
        for (int ni = 0; ni < 4; ni++)
#pragma unroll
            for (int j = 0; j < 4; j++) acc[mi][ni][j] = 0.f;

    int aoff[4];
#pragma unroll
    for (int mi = 0; mi < 4; mi++)
        aoff[mi] = (wm*64 + mi*16 + (lane & 15))*40 + (lane >> 4)*8;
    int boff[2];
#pragma unroll
    for (int tp = 0; tp < 2; tp++) {
        int tile = tp*2 + (m_idx >> 1);
        int n = wn*32 + tile*8 + row_in;
        boff[tp] = n*40 + (m_idx & 1)*8;
    }

    auto stage = [&](int ck, int bufi) {
        int c0 = ck * 16;
        for (int u = tid; u < 512; u += 256) {
            int half = u & 1, co = (u >> 1) & 127, split = u >> 8;
            const ushort_t* src = (split ? g_w2_lo : g_w2_hi) + co*128 + c0 + half*8;
            cp_async16(&a_sm[bufi][co*40 + split*16 + half*8], src);
        }
        for (int u = tid; u < 512; u += 256) {
            int half = u & 1, n = (u >> 1) & 127, split = u >> 8;
            const ushort_t* src = (split ? g_ao_lo : g_ao_hi)
                + ((size_t)b*1024 + n0 + n)*128 + c0 + half*8;
            cp_async16(&b_sm[bufi][n*40 + split*16 + half*8], src);
        }
        cp_async_commit();
    };

    stage(0, 0);
    for (int ck = 0; ck < 8; ck++) {
        const int buf = ck & 1;
        if (ck + 1 < 8) { stage(ck + 1, buf ^ 1); cp_async_wait1(); }
        else            { cp_async_wait0(); }
        __syncthreads();

        const ushort_t* ab = a_sm[buf];
        const ushort_t* bb = b_sm[buf];

        unsigned Ah[4][4], bf[4][2], bl[4][2];
#pragma unroll
        for (int mi = 0; mi < 4; mi++)
            ldmatrix_x4(Ah[mi], ab + aoff[mi]);
        {
            unsigned t4[4];
            ldmatrix_x4(t4, bb + boff[0]);
            bf[0][0]=t4[0]; bf[0][1]=t4[1]; bf[1][0]=t4[2]; bf[1][1]=t4[3];
            ldmatrix_x4(t4, bb + boff[1]);
            bf[2][0]=t4[0]; bf[2][1]=t4[1]; bf[3][0]=t4[2]; bf[3][1]=t4[3];
            ldmatrix_x4(t4, bb + boff[0] + 16);
            bl[0][0]=t4[0]; bl[0][1]=t4[1]; bl[1][0]=t4[2]; bl[1][1]=t4[3];
            ldmatrix_x4(t4, bb + boff[1] + 16);
            bl[2][0]=t4[0]; bl[2][1]=t4[1]; bl[3][0]=t4[2]; bl[3][1]=t4[3];
        }
#pragma unroll
        for (int ni = 0; ni < 4; ni++)
#pragma unroll
            for (int mi = 0; mi < 4; mi++) {
                mma_bf16(acc[mi][ni], Ah[mi], bf[ni][0], bf[ni][1]);
                mma_bf16(acc[mi][ni], Ah[mi], bl[ni][0], bl[ni][1]);
            }
#pragma unroll
        for (int mi = 0; mi < 4; mi++)
            ldmatrix_x4(Ah[mi], ab + aoff[mi] + 16);
#pragma unroll
        for (int ni = 0; ni < 4; ni++)
#pragma unroll
            for (int mi = 0; mi < 4; mi++)
                mma_bf16(acc[mi][ni], Ah[mi], bf[ni][0], bf[ni][1]);
        __syncthreads();
    }

#pragma unroll
    for (int mi = 0; mi < 4; mi++) {
        int row = wm*64 + mi*16 + (lane >> 2);
        float bv0 = bias[row], bv1 = bias[row + 8];
#pragma unroll
        for (int ni = 0; ni < 4; ni++) {
            int col = n0 + wn*32 + ni*8 + (lane & 3)*2;
            float2 v0; v0.x = acc[mi][ni][0] + bv0; v0.y = acc[mi][ni][1] + bv0;
            float2 v1; v1.x = acc[mi][ni][2] + bv1; v1.y = acc[mi][ni][3] + bv1;
            *reinterpret_cast<float2*>(&out[((size_t)b*128 + row)*1024 + col])     = v0;
            *reinterpret_cast<float2*>(&out[((size_t)b*128 + row + 8)*1024 + col]) = v1;
        }
    }
}

// =====================================================================
extern "C" void kernel_launch(void* const* d_in, const int* in_sizes, int n_in,
                              void* d_out, int out_size)
{
    const float* x      = (const float*)d_in[0];
    const float* wq     = (const float*)d_in[1];
    const float* gq     = (const float*)d_in[2];
    const float* bq     = (const float*)d_in[3];
    const float* wk     = (const float*)d_in[4];
    const float* gk     = (const float*)d_in[5];
    const float* bk     = (const float*)d_in[6];
    const float* wv     = (const float*)d_in[7];
    const float* gv     = (const float*)d_in[8];
    const float* bv     = (const float*)d_in[9];
    const float* table  = (const float*)d_in[10];
    const int*   relidx = (const int*)  d_in[11];
    const float* out_w  = (const float*)d_in[12];
    const float* out_b  = (const float*)d_in[13];
    float* out = (float*)d_out;

    prep_all_kernel<<<4864, 256>>>(x, wq, wk, wv, out_w, table, relidx); // 0
    conv_mma_kernel<<<dim3(8, 16, 3), 256>>>();                          // 1
    norm_gelu_kernel<<<dim3(16, 4, 48), 256>>>(gq, bq, gk, bk, gv, bv);  // 2
    attn_mma_kernel<<<dim3(8, 64), 256>>>();                             // 3  <- profiled
    outconv_mma_kernel<<<dim3(8, 16), 256>>>(out_b, out);                // 4
}